// round 9
// baseline (speedup 1.0000x reference)
#include <cuda_runtime.h>
#include <cstdint>

// Problem: B=1024, T=365, DYN=32, STATIC=27, U=256, 3U=768, K=288.
#define T_STEPS 365

// -------- device scratch (static; no allocation) --------
__device__ float g_igate[1024 * 256];
__device__ float g_hbuf[2][1024 * 256];
__device__ int   g_flag[16 * 4 * 8];   // flag[bt][mt][ug]

// -------- helpers --------
__device__ __forceinline__ uint32_t f2tf(float v) {
    uint32_t r;
    asm("cvt.rna.tf32.f32 %0, %1;" : "=r"(r) : "f"(v));
    return r;
}
__device__ __forceinline__ float tanh_fast(float x) {
    float r;
    asm("tanh.approx.f32 %0, %1;" : "=f"(r) : "f"(x));
    return r;
}
__device__ __forceinline__ float sig_fast(float x) {
    return fmaf(0.5f, tanh_fast(0.5f * x), 0.5f);
}
__device__ __forceinline__ void mma_tf32(float acc[4], uint32_t a0, uint32_t a1,
                                         uint32_t a2, uint32_t a3,
                                         uint32_t b0, uint32_t b1) {
    asm volatile(
        "mma.sync.aligned.m16n8k8.row.col.f32.tf32.tf32.f32 "
        "{%0,%1,%2,%3}, {%4,%5,%6,%7}, {%8,%9}, {%0,%1,%2,%3};"
        : "+f"(acc[0]), "+f"(acc[1]), "+f"(acc[2]), "+f"(acc[3])
        : "r"(a0), "r"(a1), "r"(a2), "r"(a3), "r"(b0), "r"(b1));
}

// ---------------------------------------------------------------------------
// Setup: i_gate = sigmoid(x_static @ W_sh + bias_s); reset flags.
// ---------------------------------------------------------------------------
__global__ void setup_k(const float* __restrict__ xs,
                        const float* __restrict__ wsh,
                        const float* __restrict__ bias_s) {
    int b = blockIdx.x;
    int u = threadIdx.x;
    if (b == 0) {
#pragma unroll
        for (int i = 0; i < 2; ++i)
            if (u + i * 256 < 512) g_flag[u + i * 256] = 0;
    }
    float acc = bias_s[u];
#pragma unroll
    for (int d = 0; d < 27; ++d)
        acc += xs[b * 27 + d] * wsh[d * 256 + u];
    g_igate[b * 256 + u] = sig_fast(acc);
}

// ---------------------------------------------------------------------------
// Main persistent recurrence kernel — warp-pair decoupled pipelines.
//   gang = blockIdx.x>>3 (16 gangs, 64 batch rows each)
//   ug   = blockIdx.x&7  (8 unit-groups, 32 units -> 96 gate cols each)
// Warp (8) = mt(4 m-tiles of 16 rows) x nh(2 col-halves of 48 cols).
// Pair (mt) = warps {mt, mt+4}: owns batch rows mt*16..+16 end-to-end.
// No CTA-wide sync in the loop; pairs sync via named barrier (mt+1, 64).
// Flags: g_flag[bt][mt][ug] = t+1 when producer pair (bt,ug,mt)'s rows ready.
// Smem: sW [96][304] words kt-pair-packed tf32 B-frags; sA [64][292] tf32.
// ---------------------------------------------------------------------------
#define SW_WORDS (96 * 304)          // 29184
#define SA_WORDS (64 * 292)          // 18688
#define SMEM_BYTES ((SW_WORDS + SA_WORDS) * 4)   // 191488 B

__global__ void __launch_bounds__(256, 1)
lstm_k(const float* __restrict__ xd,
       const float* __restrict__ wih,
       const float* __restrict__ whh,
       const float* __restrict__ bias,
       float* __restrict__ out) {
    extern __shared__ uint32_t smem[];
    uint32_t* sW = smem;
    uint32_t* sA = smem + SW_WORDS;

    const int tid  = threadIdx.x;
    const int lane = tid & 31;
    const int warp = tid >> 5;
    const int bt   = blockIdx.x >> 3;
    const int ug   = blockIdx.x & 7;
    const int b0   = bt * 64;
    const int U0   = ug * 32;

    const int mt = warp & 3;
    const int nh = warp >> 2;
    const int barid = mt + 1;

    // ---- one-time: pack permuted W slice [288 x 96], kt-pair uint4 layout --
    for (int idx = tid; idx < 288 * 96; idx += 256) {
        int k = idx / 96;
        int n = idx - k * 96;              // physical col 0..95
        int nhp = n / 48;
        int nn  = n - nhp * 48;
        int ntp = nn >> 3;
        int c   = nn & 7;
        int j    = ntp * 2 + (c & 1);
        int gate = j % 3;
        int unitw = (c >> 1) * 4 + j / 3;
        int gcol = gate * 256 + U0 + nhp * 16 + unitw;
        float v = (k < 256) ? whh[k * 768 + gcol] : wih[(k - 256) * 768 + gcol];
        int kt = k >> 3, kk = k & 7;
        sW[n * 304 + (kt >> 1) * 16 + (kk & 3) * 4 + (kt & 1) * 2 + (kk >> 2)]
            = f2tf(v);
    }

    // ---- zero the h region of sA (for t=0) ----
    {
        uint4 z = make_uint4(0, 0, 0, 0);
#pragma unroll
        for (int i = 0; i < 16; ++i) {
            int idx = tid + (i << 8);            // 0..4095 uint4
            int m = idx >> 6, q = idx & 63;
            *(uint4*)&sA[m * 292 + q * 4] = z;
        }
    }

    // ---- per-pair x staging geometry (own 8 rows per warp) ----
    const int xrow = mt * 16 + nh * 8 + (lane >> 2);   // local row
    const int xcc  = (lane & 3) * 8;                   // col base (2x float4)

    // ---- stage x_0 directly ----
    {
        const float* src = &xd[((size_t)(b0 + xrow) * 365 + 0) * 32 + xcc];
        float4 v0 = *(const float4*)src;
        float4 v1 = *(const float4*)(src + 4);
        uint4 w0, w1;
        w0.x = f2tf(v0.x); w0.y = f2tf(v0.y); w0.z = f2tf(v0.z); w0.w = f2tf(v0.w);
        w1.x = f2tf(v1.x); w1.y = f2tf(v1.y); w1.z = f2tf(v1.z); w1.w = f2tf(v1.w);
        *(uint4*)&sA[xrow * 292 + 256 + xcc]     = w0;
        *(uint4*)&sA[xrow * 292 + 256 + xcc + 4] = w1;
    }

    // ---- MMA role & per-thread persistent state ----
    const int gid = lane >> 2;
    const int tig = lane & 3;
    const int row0 = b0 + mt * 16 + gid;          // second row = row0 + 8
    const int ucol = U0 + nh * 16 + tig * 4;      // 4 consecutive units

    float cst[2][4], igr[2][4], bfv[4], bov[4], bgv[4];
    {
        float4 i0 = *(const float4*)&g_igate[row0 * 256 + ucol];
        float4 i1 = *(const float4*)&g_igate[(row0 + 8) * 256 + ucol];
        igr[0][0] = i0.x; igr[0][1] = i0.y; igr[0][2] = i0.z; igr[0][3] = i0.w;
        igr[1][0] = i1.x; igr[1][1] = i1.y; igr[1][2] = i1.z; igr[1][3] = i1.w;
#pragma unroll
        for (int q = 0; q < 4; ++q) {
            cst[0][q] = 0.0f; cst[1][q] = 0.0f;
            bfv[q] = bias[ucol + q];
            bov[q] = bias[256 + ucol + q];
            bgv[q] = bias[512 + ucol + q];
        }
    }

    const uint32_t* A0b = sA + (mt * 16 + gid) * 292 + tig;
    const uint32_t* A1b = A0b + 8 * 292;
    const uint32_t* wb0 = sW + (nh * 48 + gid) * 304 + tig * 4;

    const uint32_t sAsh = (uint32_t)__cvta_generic_to_shared(sA);
    int* flag_self = &g_flag[(bt * 4 + mt) * 8 + ug];
    const int* flag_poll = &g_flag[(bt * 4 + mt) * 8 + lane];   // lanes 0..7

    // h cp.async geometry: own 8 rows x 256 cols
    const int hrow_base = mt * 16 + nh * 8;

    __syncthreads();   // W packed, sA initialized (only CTA-wide sync)

    float4 px0, px1;   // prefetched x_{t+1}

    for (int t = 0; t < T_STEPS; ++t) {
        // ---- x-part MMA (ktp 16..17) on x_t staged last step ----
        float acc[6][4];
#pragma unroll
        for (int nt = 0; nt < 6; ++nt)
#pragma unroll
            for (int q = 0; q < 4; ++q) acc[nt][q] = 0.0f;

#pragma unroll
        for (int ktp = 16; ktp < 18; ++ktp) {
            uint32_t a0e = A0b[ktp * 16],      a2e = A0b[ktp * 16 + 4];
            uint32_t a1e = A1b[ktp * 16],      a3e = A1b[ktp * 16 + 4];
            uint32_t a0o = A0b[ktp * 16 + 8],  a2o = A0b[ktp * 16 + 12];
            uint32_t a1o = A1b[ktp * 16 + 8],  a3o = A1b[ktp * 16 + 12];
#pragma unroll
            for (int nt = 0; nt < 6; ++nt) {
                uint4 bq = *(const uint4*)(wb0 + nt * 8 * 304 + ktp * 16);
                mma_tf32(acc[nt], a0e, a1e, a2e, a3e, bq.x, bq.y);
                mma_tf32(acc[nt], a0o, a1o, a2o, a3o, bq.z, bq.w);
            }
        }

        // ---- prefetch x_{t+1} into registers (hide DRAM latency) ----
        if (t + 1 < T_STEPS) {
            const float* src =
                &xd[((size_t)(b0 + xrow) * 365 + (t + 1)) * 32 + xcc];
            px0 = *(const float4*)src;
            px1 = *(const float4*)(src + 4);
        }

        // ---- wait for the 8 producer pairs of this m-tile; stage h ----
        if (t > 0) {
            int done;
            do {
                int v = t;
                if (lane < 8)
                    asm volatile("ld.acquire.gpu.global.b32 %0, [%1];"
                                 : "=r"(v) : "l"(flag_poll) : "memory");
                done = __all_sync(0xffffffffu, v >= t);
            } while (!done);

            const float* hb = g_hbuf[t & 1];
#pragma unroll
            for (int i = 0; i < 16; ++i) {
                int idx = lane + (i << 5);          // 0..511
                int row = hrow_base + (idx >> 6);
                int c4  = (idx & 63) << 2;
                const float* src = &hb[(b0 + row) * 256 + c4];
                uint32_t dst = sAsh + (row * 292 + c4) * 4;
                asm volatile("cp.async.cg.shared.global [%0], [%1], 16;"
                             :: "r"(dst), "l"(src));
            }
            asm volatile("cp.async.commit_group;");
            asm volatile("cp.async.wait_group 0;");
        }
        asm volatile("bar.sync %0, 64;" :: "r"(barid) : "memory");   // b2

        // ---- h-part MMA (ktp 0..15) ----
#pragma unroll 4
        for (int ktp = 0; ktp < 16; ++ktp) {
            uint32_t a0e = A0b[ktp * 16],      a2e = A0b[ktp * 16 + 4];
            uint32_t a1e = A1b[ktp * 16],      a3e = A1b[ktp * 16 + 4];
            uint32_t a0o = A0b[ktp * 16 + 8],  a2o = A0b[ktp * 16 + 12];
            uint32_t a1o = A1b[ktp * 16 + 8],  a3o = A1b[ktp * 16 + 12];
#pragma unroll
            for (int nt = 0; nt < 6; ++nt) {
                uint4 bq = *(const uint4*)(wb0 + nt * 8 * 304 + ktp * 16);
                mma_tf32(acc[nt], a0e, a1e, a2e, a3e, bq.x, bq.y);
                mma_tf32(acc[nt], a0o, a1o, a2o, a3o, bq.z, bq.w);
            }
        }

        // ---- epilogue fully in registers ----
        if (t < T_STEPS - 1) {
            float* hb = g_hbuf[(t + 1) & 1];
#pragma unroll
            for (int r = 0; r < 2; ++r) {
                const int sb = 2 * r;
                float fg[4] = { acc[0][sb],     acc[1][sb + 1],
                                acc[3][sb],     acc[4][sb + 1] };
                float og[4] = { acc[0][sb + 1], acc[2][sb],
                                acc[3][sb + 1], acc[5][sb] };
                float gg[4] = { acc[1][sb],     acc[2][sb + 1],
                                acc[4][sb],     acc[5][sb + 1] };
                uint4 hw;
                uint32_t* hwp = &hw.x;
#pragma unroll
                for (int q = 0; q < 4; ++q) {
                    float cn = sig_fast(fg[q] + bfv[q]) * cst[r][q]
                             + igr[r][q] * tanh_fast(gg[q] + bgv[q]);
                    cst[r][q] = cn;
                    float hv = sig_fast(og[q] + bov[q]) * tanh_fast(cn);
                    hwp[q] = f2tf(hv);   // pre-rounded: consumers copy raw bits
                }
                *(uint4*)&hb[(row0 + 8 * r) * 256 + ucol] = hw;
            }

            // ---- stage x_{t+1} from prefetched registers ----
            {
                uint4 w0, w1;
                w0.x = f2tf(px0.x); w0.y = f2tf(px0.y);
                w0.z = f2tf(px0.z); w0.w = f2tf(px0.w);
                w1.x = f2tf(px1.x); w1.y = f2tf(px1.y);
                w1.z = f2tf(px1.z); w1.w = f2tf(px1.w);
                *(uint4*)&sA[xrow * 292 + 256 + xcc]     = w0;
                *(uint4*)&sA[xrow * 292 + 256 + xcc + 4] = w1;
            }

            asm volatile("bar.sync %0, 64;" :: "r"(barid) : "memory");  // b3
            if (nh == 0 && lane == 0)
                asm volatile("st.release.gpu.global.b32 [%0], %1;"
                             :: "l"(flag_self), "r"(t + 1) : "memory");
        } else {
#pragma unroll
            for (int r = 0; r < 2; ++r) {
                const int sb = 2 * r;
                float fg[4] = { acc[0][sb],     acc[1][sb + 1],
                                acc[3][sb],     acc[4][sb + 1] };
                float og[4] = { acc[0][sb + 1], acc[2][sb],
                                acc[3][sb + 1], acc[5][sb] };
                float gg[4] = { acc[1][sb],     acc[2][sb + 1],
                                acc[4][sb],     acc[5][sb + 1] };
                float hv[4];
#pragma unroll
                for (int q = 0; q < 4; ++q) {
                    float cn = sig_fast(fg[q] + bfv[q]) * cst[r][q]
                             + igr[r][q] * tanh_fast(gg[q] + bgv[q]);
                    hv[q] = sig_fast(og[q] + bov[q]) * tanh_fast(cn);
                }
                *(float4*)&out[(row0 + 8 * r) * 256 + ucol] =
                    make_float4(hv[0], hv[1], hv[2], hv[3]);
            }
        }
    }
}

// ---------------------------------------------------------------------------
extern "C" void kernel_launch(void* const* d_in, const int* in_sizes, int n_in,
                              void* d_out, int out_size) {
    const float* xd     = (const float*)d_in[0];   // x_dynamic [1024,365,32]
    const float* xs     = (const float*)d_in[1];   // x_static  [1024,27]
    const float* wih    = (const float*)d_in[2];   // weight_ih [32,768]
    const float* whh    = (const float*)d_in[3];   // weight_hh [256,768]
    const float* wsh    = (const float*)d_in[4];   // weight_sh [27,256]
    const float* bias   = (const float*)d_in[5];   // [768]
    const float* bias_s = (const float*)d_in[6];   // [256]
    float* out = (float*)d_out;                    // [1024,256]

    cudaFuncSetAttribute(lstm_k, cudaFuncAttributeMaxDynamicSharedMemorySize,
                         SMEM_BYTES);

    setup_k<<<1024, 256>>>(xs, wsh, bias_s);
    lstm_k<<<128, 256, SMEM_BYTES>>>(xd, wih, whh, bias, out);
}

// round 10
// speedup vs baseline: 1.2225x; 1.2225x over previous
#include <cuda_runtime.h>
#include <cstdint>

// Problem: B=1024, T=365, DYN=32, STATIC=27, U=256, 3U=768, K=288.
#define T_STEPS 365

// -------- device scratch (static; no allocation) --------
// h exchange buffer: [2][gang(16)][ug(8)][64 rows][36 cols] (36 = 32 + pad)
__device__ float g_igate[1024 * 256];
__device__ float g_hbuf[2][16 * 8 * 2304];

// -------- helpers --------
__device__ __forceinline__ uint32_t f2tf(float v) {
    uint32_t r;
    asm("cvt.rna.tf32.f32 %0, %1;" : "=r"(r) : "f"(v));
    return r;
}
__device__ __forceinline__ float tanh_fast(float x) {
    float r;
    asm("tanh.approx.f32 %0, %1;" : "=f"(r) : "f"(x));
    return r;
}
__device__ __forceinline__ float sig_fast(float x) {
    return fmaf(0.5f, tanh_fast(0.5f * x), 0.5f);
}
__device__ __forceinline__ void mma_tf32(float acc[4], uint32_t a0, uint32_t a1,
                                         uint32_t a2, uint32_t a3,
                                         uint32_t b0, uint32_t b1) {
    asm volatile(
        "mma.sync.aligned.m16n8k8.row.col.f32.tf32.tf32.f32 "
        "{%0,%1,%2,%3}, {%4,%5,%6,%7}, {%8,%9}, {%0,%1,%2,%3};"
        : "+f"(acc[0]), "+f"(acc[1]), "+f"(acc[2]), "+f"(acc[3])
        : "r"(a0), "r"(a1), "r"(a2), "r"(a3), "r"(b0), "r"(b1));
}
__device__ __forceinline__ void bar_wait(uint32_t mbar, int parity) {
    asm volatile(
        "{\n\t.reg .pred P;\n"
        "LW%=:\n\t"
        "mbarrier.try_wait.parity.acquire.cta.shared::cta.b64 P, [%0], %1, 0x989680;\n\t"
        "@P bra.uni LD%=;\n\t"
        "bra.uni LW%=;\n"
        "LD%=:\n\t}"
        :: "r"(mbar), "r"(parity) : "memory");
}

// ---------------------------------------------------------------------------
// Setup: i_gate = sigmoid(x_static @ W_sh + bias_s).
// ---------------------------------------------------------------------------
__global__ void setup_k(const float* __restrict__ xs,
                        const float* __restrict__ wsh,
                        const float* __restrict__ bias_s) {
    int b = blockIdx.x;
    int u = threadIdx.x;
    float acc = bias_s[u];
#pragma unroll
    for (int d = 0; d < 27; ++d)
        acc += xs[b * 27 + d] * wsh[d * 256 + u];
    g_igate[b * 256 + u] = sig_fast(acc);
}

// ---------------------------------------------------------------------------
// Main kernel: gang == cluster of 8 CTAs (fully independent gangs).
//   bt = blockIdx.x>>3 (gang, 64 batch rows), ug = rank in cluster (32 units).
// Exchange: producer pushes its OWN h chunk (64x36 fl = 9216B) via
// cp.async.bulk ... .multicast::cluster to all 8 CTAs' sA slots; completion
// via per-CTA full-mbarrier (expect_tx 8*9216); backpressure via
// empty-mbarrier (64 arrivals = 8 warps x 8 CTAs, posted post-h-MMA).
// Smem words: [0..8) mbarriers | sW 29184 (B-frags, as R7) |
//             sA_h 8*2304 (chunk layout [ug][64][36]) | sX 2304 ([64][36])
// ---------------------------------------------------------------------------
#define BAR_FULL_B  0
#define BAR_EMPTY_B 8
#define SW_OFF   8
#define SW_WORDS 29184
#define SA_OFF   (SW_OFF + SW_WORDS)          // 29192
#define SX_OFF   (SA_OFF + 8 * 2304)          // 47624
#define TOT_W    (SX_OFF + 2304)              // 49928
#define SMEM_BYTES (TOT_W * 4)                // 199712
#define CHUNK_W  2304
#define CHUNK_B  9216
#define TX_TOTAL (8 * CHUNK_B)                // 73728

__global__ void __launch_bounds__(256, 1) __cluster_dims__(8, 1, 1)
lstm_k(const float* __restrict__ xd,
       const float* __restrict__ wih,
       const float* __restrict__ whh,
       const float* __restrict__ bias,
       float* __restrict__ out) {
    extern __shared__ uint32_t smem[];
    uint32_t* sW = smem + SW_OFF;
    uint32_t* sA = smem + SA_OFF;
    uint32_t* sX = smem + SX_OFF;

    const uint32_t smem_sh = (uint32_t)__cvta_generic_to_shared(smem);
    const uint32_t bar_full  = smem_sh + BAR_FULL_B;
    const uint32_t bar_empty = smem_sh + BAR_EMPTY_B;

    const int tid  = threadIdx.x;
    const int lane = tid & 31;
    const int warp = tid >> 5;
    const int bt   = blockIdx.x >> 3;
    const int ug   = blockIdx.x & 7;
    const int b0   = bt * 64;
    const int U0   = ug * 32;
    const int mt   = warp & 3;
    const int nh   = warp >> 2;

    // ---- init mbarriers (before any cluster traffic) ----
    if (tid == 0) {
        asm volatile("mbarrier.init.shared.b64 [%0], %1;"
                     :: "r"(bar_full), "r"(1) : "memory");
        asm volatile("mbarrier.init.shared.b64 [%0], %1;"
                     :: "r"(bar_empty), "r"(64) : "memory");
    }

    // ---- one-time: pack permuted W slice [288 x 96], kt-pair uint4 layout --
    for (int idx = tid; idx < 288 * 96; idx += 256) {
        int k = idx / 96;
        int n = idx - k * 96;
        int nhp = n / 48;
        int nn  = n - nhp * 48;
        int ntp = nn >> 3;
        int c   = nn & 7;
        int j    = ntp * 2 + (c & 1);
        int gate = j % 3;
        int unitw = (c >> 1) * 4 + j / 3;
        int gcol = gate * 256 + U0 + nhp * 16 + unitw;
        float v = (k < 256) ? whh[k * 768 + gcol] : wih[(k - 256) * 768 + gcol];
        int kt = k >> 3, kk = k & 7;
        sW[n * 304 + (kt >> 1) * 16 + (kk & 3) * 4 + (kt & 1) * 2 + (kk >> 2)]
            = f2tf(v);
    }

    // ---- zero sA h region (h_0 = 0) ----
    {
        uint4 z = make_uint4(0, 0, 0, 0);
        for (int i = tid; i < 8 * 2304 / 4; i += 256)
            *(uint4*)&sA[i * 4] = z;
    }

    // ---- x staging geometry: warp stages its mt's 16 rows (dup w/ sibling) --
    const int xrow = mt * 16 + (lane >> 1);      // local row
    const int xco  = (lane & 1) * 16;            // col base, 16 cols per lane

    // ---- stage x_0 ----
    {
        const float* src = &xd[((size_t)(b0 + xrow) * 365 + 0) * 32 + xco];
#pragma unroll
        for (int c = 0; c < 4; ++c) {
            float4 v = *(const float4*)(src + c * 4);
            uint4 w;
            w.x = f2tf(v.x); w.y = f2tf(v.y); w.z = f2tf(v.z); w.w = f2tf(v.w);
            *(uint4*)&sX[xrow * 36 + xco + c * 4] = w;
        }
    }

    // ---- MMA role & per-thread persistent state ----
    const int gid = lane >> 2;
    const int tig = lane & 3;
    const int lrow0 = mt * 16 + gid;              // local rows lrow0, lrow0+8
    const int row0  = b0 + lrow0;
    const int ucol  = U0 + nh * 16 + tig * 4;

    float cst[2][4], igr[2][4], bfv[4], bov[4], bgv[4];
    {
        float4 i0 = *(const float4*)&g_igate[row0 * 256 + ucol];
        float4 i1 = *(const float4*)&g_igate[(row0 + 8) * 256 + ucol];
        igr[0][0] = i0.x; igr[0][1] = i0.y; igr[0][2] = i0.z; igr[0][3] = i0.w;
        igr[1][0] = i1.x; igr[1][1] = i1.y; igr[1][2] = i1.z; igr[1][3] = i1.w;
#pragma unroll
        for (int q = 0; q < 4; ++q) {
            cst[0][q] = 0.0f; cst[1][q] = 0.0f;
            bfv[q] = bias[ucol + q];
            bov[q] = bias[256 + ucol + q];
            bgv[q] = bias[512 + ucol + q];
        }
    }

    const uint32_t* Ah0 = sA + lrow0 * 36 + tig;          // + chunk*2304 + half*16
    const uint32_t* Ah1 = Ah0 + 8 * 36;
    const uint32_t* Ax0 = sX + lrow0 * 36 + tig;
    const uint32_t* Ax1 = Ax0 + 8 * 36;
    const uint32_t* wb0 = sW + (nh * 48 + gid) * 304 + tig * 4;

    // producer gmem chunk base (floats) & multicast smem dst
    const int chunk_id = bt * 8 + ug;
    const uint32_t mc_dst = smem_sh + (SA_OFF + ug * CHUNK_W) * 4;
    // epilogue STG offsets within chunk
    const int ecol = nh * 16 + tig * 4;

    __syncthreads();
    // cluster sync: all peers' mbarriers initialized before any remote arrive
    asm volatile("barrier.cluster.arrive.aligned;" ::: "memory");
    asm volatile("barrier.cluster.wait.aligned;" ::: "memory");

    int full_ph = 0, empty_ph = 0;
    float4 px[4];

    for (int t = 0; t < T_STEPS; ++t) {
        // ---- x-part MMA (ktp 16..17, chunk sX) ----
        float acc[6][4];
#pragma unroll
        for (int nt = 0; nt < 6; ++nt)
#pragma unroll
            for (int q = 0; q < 4; ++q) acc[nt][q] = 0.0f;

#pragma unroll
        for (int half = 0; half < 2; ++half) {
            const uint32_t* a0p = Ax0 + half * 16;
            const uint32_t* a1p = Ax1 + half * 16;
            uint32_t a0e = a0p[0], a2e = a0p[4], a0o = a0p[8],  a2o = a0p[12];
            uint32_t a1e = a1p[0], a3e = a1p[4], a1o = a1p[8],  a3o = a1p[12];
#pragma unroll
            for (int nt = 0; nt < 6; ++nt) {
                uint4 bq = *(const uint4*)(wb0 + nt * 8 * 304 + (16 + half) * 16);
                mma_tf32(acc[nt], a0e, a1e, a2e, a3e, bq.x, bq.y);
                mma_tf32(acc[nt], a0o, a1o, a2o, a3o, bq.z, bq.w);
            }
        }

        // ---- prefetch x_{t+1} ----
        if (t + 1 < T_STEPS) {
            const float* src =
                &xd[((size_t)(b0 + xrow) * 365 + (t + 1)) * 32 + xco];
#pragma unroll
            for (int c = 0; c < 4; ++c) px[c] = *(const float4*)(src + c * 4);
        }

        // ---- wait for all 8 h-chunks (multicast deliveries) ----
        if (t > 0) {
            bar_wait(bar_full, full_ph);
            full_ph ^= 1;
        }

        // ---- h-part MMA (ktp 0..15, chunked sA) ----
#pragma unroll 4
        for (int ktp = 0; ktp < 16; ++ktp) {
            const uint32_t* a0p = Ah0 + (ktp >> 1) * CHUNK_W + (ktp & 1) * 16;
            const uint32_t* a1p = Ah1 + (ktp >> 1) * CHUNK_W + (ktp & 1) * 16;
            uint32_t a0e = a0p[0], a2e = a0p[4], a0o = a0p[8],  a2o = a0p[12];
            uint32_t a1e = a1p[0], a3e = a1p[4], a1o = a1p[8],  a3o = a1p[12];
#pragma unroll
            for (int nt = 0; nt < 6; ++nt) {
                uint4 bq = *(const uint4*)(wb0 + nt * 8 * 304 + ktp * 16);
                mma_tf32(acc[nt], a0e, a1e, a2e, a3e, bq.x, bq.y);
                mma_tf32(acc[nt], a0o, a1o, a2o, a3o, bq.z, bq.w);
            }
        }

        if (t < T_STEPS - 1) {
            // ---- post expect_tx for next phase, then release empties ----
            if (warp == 0 && lane == 0)
                asm volatile(
                    "mbarrier.arrive.expect_tx.shared.b64 _, [%0], %1;"
                    :: "r"(bar_full), "r"(TX_TOTAL) : "memory");
            if (lane < 8) {
                asm volatile(
                    "{\n\t.reg .b32 rA;\n\t"
                    "mapa.shared::cluster.u32 rA, %0, %1;\n\t"
                    "mbarrier.arrive.shared::cluster.b64 _, [rA];\n\t}"
                    :: "r"(bar_empty), "r"(lane) : "memory");
            }

            // ---- epilogue: h_{t+1} (tf32 bits) -> own gmem chunk ----
            float* hc = &g_hbuf[(t + 1) & 1][chunk_id * CHUNK_W];
#pragma unroll
            for (int r = 0; r < 2; ++r) {
                const int sb = 2 * r;
                float fg[4] = { acc[0][sb],     acc[1][sb + 1],
                                acc[3][sb],     acc[4][sb + 1] };
                float og[4] = { acc[0][sb + 1], acc[2][sb],
                                acc[3][sb + 1], acc[5][sb] };
                float gg[4] = { acc[1][sb],     acc[2][sb + 1],
                                acc[4][sb],     acc[5][sb + 1] };
                uint4 hw;
                uint32_t* hwp = &hw.x;
#pragma unroll
                for (int q = 0; q < 4; ++q) {
                    float cn = sig_fast(fg[q] + bfv[q]) * cst[r][q]
                             + igr[r][q] * tanh_fast(gg[q] + bgv[q]);
                    cst[r][q] = cn;
                    float hv = sig_fast(og[q] + bov[q]) * tanh_fast(cn);
                    hwp[q] = f2tf(hv);
                }
                *(uint4*)&hc[(lrow0 + 8 * r) * 36 + ecol] = hw;
            }

            // ---- stage x_{t+1} (before the CTA barrier) ----
#pragma unroll
            for (int c = 0; c < 4; ++c) {
                uint4 w;
                w.x = f2tf(px[c].x); w.y = f2tf(px[c].y);
                w.z = f2tf(px[c].z); w.w = f2tf(px[c].w);
                *(uint4*)&sX[xrow * 36 + xco + c * 4] = w;
            }

            __syncthreads();   // all STGs of the chunk done

            // ---- elected: publish chunk via bulk multicast ----
            if (tid == 0) {
                __threadfence();
                asm volatile("fence.proxy.async.global;" ::: "memory");
                bar_wait(bar_empty, empty_ph);        // all peers past h-MMA
                empty_ph ^= 1;
                const float* src = &g_hbuf[(t + 1) & 1][chunk_id * CHUNK_W];
                asm volatile(
                    "cp.async.bulk.shared::cluster.global"
                    ".mbarrier::complete_tx::bytes.multicast::cluster "
                    "[%0], [%1], %2, [%3], %4;"
                    :: "r"(mc_dst), "l"(src), "r"(CHUNK_B),
                       "r"(bar_full), "h"((uint16_t)0xFF)
                    : "memory");
            }
        } else {
            // ---- final step: write h_365 to out (fp32, unrounded) ----
#pragma unroll
            for (int r = 0; r < 2; ++r) {
                const int sb = 2 * r;
                float fg[4] = { acc[0][sb],     acc[1][sb + 1],
                                acc[3][sb],     acc[4][sb + 1] };
                float og[4] = { acc[0][sb + 1], acc[2][sb],
                                acc[3][sb + 1], acc[5][sb] };
                float gg[4] = { acc[1][sb],     acc[2][sb + 1],
                                acc[4][sb],     acc[5][sb + 1] };
                float hv[4];
#pragma unroll
                for (int q = 0; q < 4; ++q) {
                    float cn = sig_fast(fg[q] + bfv[q]) * cst[r][q]
                             + igr[r][q] * tanh_fast(gg[q] + bgv[q]);
                    hv[q] = sig_fast(og[q] + bov[q]) * tanh_fast(cn);
                }
                *(float4*)&out[(row0 + 8 * r) * 256 + ucol] =
                    make_float4(hv[0], hv[1], hv[2], hv[3]);
            }
        }
    }

    // cluster must not retire CTAs while peers' multicasts may target them
    asm volatile("barrier.cluster.arrive.aligned;" ::: "memory");
    asm volatile("barrier.cluster.wait.aligned;" ::: "memory");
}

// ---------------------------------------------------------------------------
extern "C" void kernel_launch(void* const* d_in, const int* in_sizes, int n_in,
                              void* d_out, int out_size) {
    const float* xd     = (const float*)d_in[0];   // x_dynamic [1024,365,32]
    const float* xs     = (const float*)d_in[1];   // x_static  [1024,27]
    const float* wih    = (const float*)d_in[2];   // weight_ih [32,768]
    const float* whh    = (const float*)d_in[3];   // weight_hh [256,768]
    const float* wsh    = (const float*)d_in[4];   // weight_sh [27,256]
    const float* bias   = (const float*)d_in[5];   // [768]
    const float* bias_s = (const float*)d_in[6];   // [256]
    float* out = (float*)d_out;                    // [1024,256]

    cudaFuncSetAttribute(lstm_k, cudaFuncAttributeMaxDynamicSharedMemorySize,
                         SMEM_BYTES);

    setup_k<<<1024, 256>>>(xs, wsh, bias_s);
    lstm_k<<<128, 256, SMEM_BYTES>>>(xd, wih, whh, bias, out);
}

// round 12
// speedup vs baseline: 1.7270x; 1.4127x over previous
#include <cuda_runtime.h>
#include <cstdint>

// Problem: B=1024, T=365, DYN=32, STATIC=27, U=256, 3U=768, K=288.
#define T_STEPS 365

// -------- device scratch (static; no allocation) --------
__device__ float g_igate[1024 * 256];
__device__ float g_hbuf[2][1024 * 256];
__device__ int   g_flag[16 * 64];    // flag[bt*64 + ug*8], 32B apart

// -------- helpers --------
__device__ __forceinline__ uint32_t f2tf(float v) {
    uint32_t r;
    asm("cvt.rna.tf32.f32 %0, %1;" : "=r"(r) : "f"(v));
    return r;
}
__device__ __forceinline__ float tanh_fast(float x) {
    float r;
    asm("tanh.approx.f32 %0, %1;" : "=f"(r) : "f"(x));
    return r;
}
__device__ __forceinline__ float sig_fast(float x) {
    return fmaf(0.5f, tanh_fast(0.5f * x), 0.5f);
}
__device__ __forceinline__ void mma_tf32(float acc[4], uint32_t a0, uint32_t a1,
                                         uint32_t a2, uint32_t a3,
                                         uint32_t b0, uint32_t b1) {
    asm volatile(
        "mma.sync.aligned.m16n8k8.row.col.f32.tf32.tf32.f32 "
        "{%0,%1,%2,%3}, {%4,%5,%6,%7}, {%8,%9}, {%0,%1,%2,%3};"
        : "+f"(acc[0]), "+f"(acc[1]), "+f"(acc[2]), "+f"(acc[3])
        : "r"(a0), "r"(a1), "r"(a2), "r"(a3), "r"(b0), "r"(b1));
}

// ---------------------------------------------------------------------------
// Setup: i_gate = sigmoid(x_static @ W_sh + bias_s); reset flags.
// ---------------------------------------------------------------------------
__global__ void setup_k(const float* __restrict__ xs,
                        const float* __restrict__ wsh,
                        const float* __restrict__ bias_s) {
    int b = blockIdx.x;
    int u = threadIdx.x;
    if (b == 0) {
#pragma unroll
        for (int i = 0; i < 4; ++i) g_flag[u + i * 256] = 0;
    }
    float acc = bias_s[u];
#pragma unroll
    for (int d = 0; d < 27; ++d)
        acc += xs[b * 27 + d] * wsh[d * 256 + u];
    g_igate[b * 256 + u] = sig_fast(acc);
}

// ---------------------------------------------------------------------------
// Main persistent recurrence kernel (R7 skeleton + K-split warp tiling).
//   gang = blockIdx.x>>3 (16 gangs, 64 batch rows), ug = blockIdx.x&7.
// Warp w: mt2 = w&1 (rows mt2*32..+32, 2 m-tiles), nh = (w>>1)&1 (48 cols),
//         kh = w>>2 (K-half: kh=0 -> ktp 0..8, kh=1 -> ktp 9..17 incl x).
// kh=1 partials reduced into kh=0 accs via padded smem region; epilogue on
// kh=0 warps (4 rows x 4 units/thread); kh=1 warps stage x_{t+1} meanwhile.
// Smem: sW [96][304] kt-pair-packed tf32 B-frags | sA [64][292] tf32 |
//       red [128][52] fp32 partials (conflict-free via 52 stride).
// ---------------------------------------------------------------------------
#define SW_WORDS (96 * 304)                   // 29184
#define SA_WORDS (64 * 292)                   // 18688
#define RED_OFF  (SW_WORDS + SA_WORDS)        // 47872
#define TOT_W    (RED_OFF + 128 * 52)         // 54528
#define SMEM_BYTES (TOT_W * 4)                // 218112

__global__ void __launch_bounds__(256, 1)
lstm_k(const float* __restrict__ xd,
       const float* __restrict__ wih,
       const float* __restrict__ whh,
       const float* __restrict__ bias,
       float* __restrict__ out) {
    extern __shared__ uint32_t smem[];
    uint32_t* sW = smem;
    uint32_t* sA = smem + SW_WORDS;
    float*    red = (float*)(smem + RED_OFF);

    const int tid  = threadIdx.x;
    const int lane = tid & 31;
    const int warp = tid >> 5;
    const int bt   = blockIdx.x >> 3;
    const int ug   = blockIdx.x & 7;
    const int b0   = bt * 64;
    const int U0   = ug * 32;

    const int mt2 = warp & 1;
    const int nh  = (warp >> 1) & 1;
    const int kh  = warp >> 2;
    const int p   = warp & 3;          // reduction pair id

    // ---- one-time: pack permuted W slice [288 x 96], kt-pair uint4 layout --
    // (permutation identical to R7: thread's 12 C-cols = 4 units x {f,o,g})
    for (int idx = tid; idx < 288 * 96; idx += 256) {
        int k = idx / 96;
        int n = idx - k * 96;              // physical col 0..95
        int nhp = n / 48;
        int nn  = n - nhp * 48;
        int ntp = nn >> 3;
        int c   = nn & 7;
        int j    = ntp * 2 + (c & 1);
        int gate = j % 3;
        int unitw = (c >> 1) * 4 + j / 3;
        int gcol = gate * 256 + U0 + nhp * 16 + unitw;
        float v = (k < 256) ? whh[k * 768 + gcol] : wih[(k - 256) * 768 + gcol];
        int kt = k >> 3, kk = k & 7;
        sW[n * 304 + (kt >> 1) * 16 + (kk & 3) * 4 + (kt & 1) * 2 + (kk >> 2)]
            = f2tf(v);
    }

    // ---- zero h region of sA (h_0 = 0) ----
    {
        uint4 z = make_uint4(0, 0, 0, 0);
#pragma unroll
        for (int i = 0; i < 16; ++i) {
            int idx = tid + (i << 8);            // 0..4095 uint4
            int m = idx >> 6, q = idx & 63;
            *(uint4*)&sA[m * 292 + q * 4] = z;
        }
    }

    // ---- x staging geometry (kh=1 warps, 128 threads, 16 floats each) ----
    const int wtid = (warp - 4) * 32 + lane;   // valid when kh==1
    const int xrow = wtid >> 1;                // local row 0..63
    const int xco  = (wtid & 1) * 16;          // col base 0/16

    // ---- stage x_0 (kh=1 warps) ----
    if (kh == 1) {
        const float* src = &xd[((size_t)(b0 + xrow) * 365 + 0) * 32 + xco];
#pragma unroll
        for (int c = 0; c < 4; ++c) {
            float4 v = *(const float4*)(src + c * 4);
            uint4 w;
            w.x = f2tf(v.x); w.y = f2tf(v.y); w.z = f2tf(v.z); w.w = f2tf(v.w);
            *(uint4*)&sA[xrow * 292 + 256 + xco + c * 4] = w;
        }
    }

    // ---- MMA role & per-thread persistent state ----
    const int gid = lane >> 2;
    const int tig = lane & 3;
    const int rbase = b0 + mt2 * 32 + gid;       // +8/+16/+24 for other rows
    const int ucol  = U0 + nh * 16 + tig * 4;    // 4 consecutive units

    float cst[4][4], igr[4][4], bfv[4], bov[4], bgv[4];
    if (kh == 0) {
#pragma unroll
        for (int r = 0; r < 4; ++r) {
            float4 iv = *(const float4*)&g_igate[(rbase + r * 8) * 256 + ucol];
            igr[r][0] = iv.x; igr[r][1] = iv.y; igr[r][2] = iv.z; igr[r][3] = iv.w;
#pragma unroll
            for (int q = 0; q < 4; ++q) cst[r][q] = 0.0f;
        }
#pragma unroll
        for (int q = 0; q < 4; ++q) {
            bfv[q] = bias[ucol + q];
            bov[q] = bias[256 + ucol + q];
            bgv[q] = bias[512 + ucol + q];
        }
    }

    // A-frag pointers: m-tile a = rows mt2*32..+16, m-tile b = +16..+32
    const uint32_t* Aa0 = sA + (mt2 * 32 + gid) * 292 + tig;
    const uint32_t* Aa1 = Aa0 + 8 * 292;
    const uint32_t* Ab0 = Aa0 + 16 * 292;
    const uint32_t* Ab1 = Aa0 + 24 * 292;
    const uint32_t* wb0 = sW + (nh * 48 + gid) * 304 + tig * 4;

    const uint32_t sAsh = (uint32_t)__cvta_generic_to_shared(sA);
    int* flag_self = &g_flag[bt * 64 + ug * 8];
    const int* flag_w = &g_flag[bt * 64 + warp * 8];

    float* redp = &red[(p * 32 + lane) * 52];

    __syncthreads();   // W packed, sA initialized

    float4 px[4];

    for (int t = 0; t < T_STEPS; ++t) {
        float acc[2][6][4];
#pragma unroll
        for (int m2 = 0; m2 < 2; ++m2)
#pragma unroll
            for (int nt = 0; nt < 6; ++nt)
#pragma unroll
                for (int q = 0; q < 4; ++q) acc[m2][nt][q] = 0.0f;

        // ---- kh=1: x-part MMA (ktp 16,17) + prefetch x_{t+1} ----
        if (kh == 1) {
#pragma unroll
            for (int ktp = 16; ktp < 18; ++ktp) {
                uint32_t aAe0 = Aa0[ktp * 16],     aAe2 = Aa0[ktp * 16 + 4];
                uint32_t aAe1 = Aa1[ktp * 16],     aAe3 = Aa1[ktp * 16 + 4];
                uint32_t aAo0 = Aa0[ktp * 16 + 8], aAo2 = Aa0[ktp * 16 + 12];
                uint32_t aAo1 = Aa1[ktp * 16 + 8], aAo3 = Aa1[ktp * 16 + 12];
                uint32_t aBe0 = Ab0[ktp * 16],     aBe2 = Ab0[ktp * 16 + 4];
                uint32_t aBe1 = Ab1[ktp * 16],     aBe3 = Ab1[ktp * 16 + 4];
                uint32_t aBo0 = Ab0[ktp * 16 + 8], aBo2 = Ab0[ktp * 16 + 12];
                uint32_t aBo1 = Ab1[ktp * 16 + 8], aBo3 = Ab1[ktp * 16 + 12];
#pragma unroll
                for (int nt = 0; nt < 6; ++nt) {
                    uint4 bq = *(const uint4*)(wb0 + nt * 8 * 304 + ktp * 16);
                    mma_tf32(acc[0][nt], aAe0, aAe1, aAe2, aAe3, bq.x, bq.y);
                    mma_tf32(acc[0][nt], aAo0, aAo1, aAo2, aAo3, bq.z, bq.w);
                    mma_tf32(acc[1][nt], aBe0, aBe1, aBe2, aBe3, bq.x, bq.y);
                    mma_tf32(acc[1][nt], aBo0, aBo1, aBo2, aBo3, bq.z, bq.w);
                }
            }
            if (t + 1 < T_STEPS) {
                const float* src =
                    &xd[((size_t)(b0 + xrow) * 365 + (t + 1)) * 32 + xco];
#pragma unroll
                for (int c = 0; c < 4; ++c) px[c] = *(const float4*)(src + c * 4);
            }
        }

        // ---- all warps: poll producer `warp`, cp.async its h chunk ----
        if (t > 0) {
            int v;
            do {
                asm volatile("ld.acquire.gpu.global.b32 %0, [%1];"
                             : "=r"(v) : "l"(flag_w) : "memory");
            } while (v < t);
            const float* hb = g_hbuf[t & 1];
#pragma unroll
            for (int i = 0; i < 16; ++i) {
                int idx = lane + (i << 5);        // 0..511
                int row = idx >> 3;
                int seg = (idx & 7) << 2;
                const float* src = &hb[(b0 + row) * 256 + warp * 32 + seg];
                uint32_t dst = sAsh + (row * 292 + warp * 32 + seg) * 4;
                asm volatile("cp.async.cg.shared.global [%0], [%1], 16;"
                             :: "r"(dst), "l"(src));
            }
            asm volatile("cp.async.commit_group;");
            asm volatile("cp.async.wait_group 0;");
        }
        __syncthreads();                                   // s3: h staged

        // ---- h-part MMA: kh=0 -> ktp 0..8, kh=1 -> ktp 9..15 ----
        {
            const int k0 = kh ? 9 : 0;
            const int k1 = kh ? 16 : 9;
#pragma unroll 3
            for (int ktp = k0; ktp < k1; ++ktp) {
                uint32_t aAe0 = Aa0[ktp * 16],     aAe2 = Aa0[ktp * 16 + 4];
                uint32_t aAe1 = Aa1[ktp * 16],     aAe3 = Aa1[ktp * 16 + 4];
                uint32_t aAo0 = Aa0[ktp * 16 + 8], aAo2 = Aa0[ktp * 16 + 12];
                uint32_t aAo1 = Aa1[ktp * 16 + 8], aAo3 = Aa1[ktp * 16 + 12];
                uint32_t aBe0 = Ab0[ktp * 16],     aBe2 = Ab0[ktp * 16 + 4];
                uint32_t aBe1 = Ab1[ktp * 16],     aBe3 = Ab1[ktp * 16 + 4];
                uint32_t aBo0 = Ab0[ktp * 16 + 8], aBo2 = Ab0[ktp * 16 + 12];
                uint32_t aBo1 = Ab1[ktp * 16 + 8], aBo3 = Ab1[ktp * 16 + 12];
#pragma unroll
                for (int nt = 0; nt < 6; ++nt) {
                    uint4 bq = *(const uint4*)(wb0 + nt * 8 * 304 + ktp * 16);
                    mma_tf32(acc[0][nt], aAe0, aAe1, aAe2, aAe3, bq.x, bq.y);
                    mma_tf32(acc[0][nt], aAo0, aAo1, aAo2, aAo3, bq.z, bq.w);
                    mma_tf32(acc[1][nt], aBe0, aBe1, aBe2, aBe3, bq.x, bq.y);
                    mma_tf32(acc[1][nt], aBo0, aBo1, aBo2, aBo3, bq.z, bq.w);
                }
            }
        }

        // ---- kh=1: store partials ----
        if (kh == 1) {
#pragma unroll
            for (int m2 = 0; m2 < 2; ++m2)
#pragma unroll
                for (int nt = 0; nt < 6; ++nt)
                    *(float4*)&redp[(m2 * 6 + nt) * 4] =
                        make_float4(acc[m2][nt][0], acc[m2][nt][1],
                                    acc[m2][nt][2], acc[m2][nt][3]);
        }
        __syncthreads();                                   // s_red

        if (kh == 0) {
            // ---- reduce + epilogue (4 rows x 4 units per thread) ----
#pragma unroll
            for (int m2 = 0; m2 < 2; ++m2)
#pragma unroll
                for (int nt = 0; nt < 6; ++nt) {
                    float4 pv = *(const float4*)&redp[(m2 * 6 + nt) * 4];
                    acc[m2][nt][0] += pv.x; acc[m2][nt][1] += pv.y;
                    acc[m2][nt][2] += pv.z; acc[m2][nt][3] += pv.w;
                }

            const bool last = (t == T_STEPS - 1);
            float* hb = last ? out : g_hbuf[(t + 1) & 1];
#pragma unroll
            for (int m2 = 0; m2 < 2; ++m2) {
#pragma unroll
                for (int rr = 0; rr < 2; ++rr) {
                    const int r  = m2 * 2 + rr;
                    const int sb = 2 * rr;
                    float fg[4] = { acc[m2][0][sb],     acc[m2][1][sb + 1],
                                    acc[m2][3][sb],     acc[m2][4][sb + 1] };
                    float og[4] = { acc[m2][0][sb + 1], acc[m2][2][sb],
                                    acc[m2][3][sb + 1], acc[m2][5][sb] };
                    float gg[4] = { acc[m2][1][sb],     acc[m2][2][sb + 1],
                                    acc[m2][4][sb],     acc[m2][5][sb + 1] };
                    const int grow = rbase + m2 * 16 + rr * 8;
                    if (!last) {
                        uint4 hw;
                        uint32_t* hwp = &hw.x;
#pragma unroll
                        for (int q = 0; q < 4; ++q) {
                            float cn = sig_fast(fg[q] + bfv[q]) * cst[r][q]
                                     + igr[r][q] * tanh_fast(gg[q] + bgv[q]);
                            cst[r][q] = cn;
                            float hv = sig_fast(og[q] + bov[q]) * tanh_fast(cn);
                            hwp[q] = f2tf(hv);   // pre-rounded tf32 bits
                        }
                        *(uint4*)&hb[grow * 256 + ucol] = hw;
                    } else {
                        float hv[4];
#pragma unroll
                        for (int q = 0; q < 4; ++q) {
                            float cn = sig_fast(fg[q] + bfv[q]) * cst[r][q]
                                     + igr[r][q] * tanh_fast(gg[q] + bgv[q]);
                            hv[q] = sig_fast(og[q] + bov[q]) * tanh_fast(cn);
                        }
                        *(float4*)&hb[grow * 256 + ucol] =
                            make_float4(hv[0], hv[1], hv[2], hv[3]);
                    }
                }
            }
        } else {
            // ---- kh=1: stage x_{t+1} from prefetched registers ----
            if (t + 1 < T_STEPS) {
#pragma unroll
                for (int c = 0; c < 4; ++c) {
                    uint4 w;
                    w.x = f2tf(px[c].x); w.y = f2tf(px[c].y);
                    w.z = f2tf(px[c].z); w.w = f2tf(px[c].w);
                    *(uint4*)&sA[xrow * 292 + 256 + xco + c * 4] = w;
                }
            }
        }

        __syncthreads();                                   // s4: loop boundary
        if (t < T_STEPS - 1 && tid == 0)
            asm volatile("st.release.gpu.global.b32 [%0], %1;"
                         :: "l"(flag_self), "r"(t + 1) : "memory");
    }
}

// ---------------------------------------------------------------------------
extern "C" void kernel_launch(void* const* d_in, const int* in_sizes, int n_in,
                              void* d_out, int out_size) {
    const float* xd     = (const float*)d_in[0];   // x_dynamic [1024,365,32]
    const float* xs     = (const float*)d_in[1];   // x_static  [1024,27]
    const float* wih    = (const float*)d_in[2];   // weight_ih [32,768]
    const float* whh    = (const float*)d_in[3];   // weight_hh [256,768]
    const float* wsh    = (const float*)d_in[4];   // weight_sh [27,256]
    const float* bias   = (const float*)d_in[5];   // [768]
    const float* bias_s = (const float*)d_in[6];   // [256]
    float* out = (float*)d_out;                    // [1024,256]

    cudaFuncSetAttribute(lstm_k, cudaFuncAttributeMaxDynamicSharedMemorySize,
                         SMEM_BYTES);

    setup_k<<<1024, 256>>>(xs, wsh, bias_s);
    lstm_k<<<128, 256, SMEM_BYTES>>>(xd, wih, whh, bias, out);
}

// round 13
// speedup vs baseline: 2.4758x; 1.4335x over previous
#include <cuda_runtime.h>
#include <cuda_fp16.h>
#include <cstdint>

// Problem: B=1024, T=365, DYN=32, STATIC=27, U=256, 3U=768, K=288.
#define T_STEPS 365

// -------- device scratch (static; no allocation) --------
__device__ float  g_igate[1024 * 256];
__device__ __half g_hbuf[2][1024 * 256];
__device__ int    g_flag[16 * 64];    // flag[bt*64 + ug*8], 32B apart

// -------- helpers --------
__device__ __forceinline__ float tanh_fast(float x) {
    float r;
    asm("tanh.approx.f32 %0, %1;" : "=f"(r) : "f"(x));
    return r;
}
__device__ __forceinline__ float sig_fast(float x) {
    return fmaf(0.5f, tanh_fast(0.5f * x), 0.5f);
}
__device__ __forceinline__ uint32_t pack_h2(float lo, float hi) {
    __half2 h = __floats2half2_rn(lo, hi);
    return *(uint32_t*)&h;
}
__device__ __forceinline__ void mma_f16(float acc[4],
                                        uint32_t a0, uint32_t a1,
                                        uint32_t a2, uint32_t a3,
                                        uint32_t b0, uint32_t b1) {
    asm volatile(
        "mma.sync.aligned.m16n8k16.row.col.f32.f16.f16.f32 "
        "{%0,%1,%2,%3}, {%4,%5,%6,%7}, {%8,%9}, {%0,%1,%2,%3};"
        : "+f"(acc[0]), "+f"(acc[1]), "+f"(acc[2]), "+f"(acc[3])
        : "r"(a0), "r"(a1), "r"(a2), "r"(a3), "r"(b0), "r"(b1));
}

// ---------------------------------------------------------------------------
// Setup: i_gate = sigmoid(x_static @ W_sh + bias_s); reset flags.
// ---------------------------------------------------------------------------
__global__ void setup_k(const float* __restrict__ xs,
                        const float* __restrict__ wsh,
                        const float* __restrict__ bias_s) {
    int b = blockIdx.x;
    int u = threadIdx.x;
    if (b == 0) {
#pragma unroll
        for (int i = 0; i < 4; ++i) g_flag[u + i * 256] = 0;
    }
    float acc = bias_s[u];
#pragma unroll
    for (int d = 0; d < 27; ++d)
        acc += xs[b * 27 + d] * wsh[d * 256 + u];
    g_igate[b * 256 + u] = sig_fast(acc);
}

// ---------------------------------------------------------------------------
// Main persistent recurrence kernel — R7 skeleton, fp16 MMA data plane.
//   gang = blockIdx.x>>3 (16 gangs, 64 batch rows), ug = blockIdx.x&7.
// Warp (8) = mt(4 m-tiles of 16 rows) x nh(2 col-halves of 48 cols).
// MMA: m16n8k16.f16.f32; K=288 -> 18 k-steps of 16, paired as 9 ksp.
// Column permutation (as R7): thread's 12 C-cols = 4 units x {f,o,g}.
// Smem: sW [96][144] words f16 B-frags (uint4 per (n-frag,ksp), stride 144
//       -> conflict-free LDS.128); sA [64][148] words f16 rows (h words
//       0..128, x words 128..144; stride 148 -> conflict-free ldmatrix).
// ---------------------------------------------------------------------------
#define SWS 144
#define SAS 148
#define SW_WORDS (96 * SWS)                   // 13824
#define SA_WORDS (64 * SAS)                   // 9472
#define SMEM_BYTES ((SW_WORDS + SA_WORDS) * 4)   // 93184

__global__ void __launch_bounds__(256, 1)
lstm_k(const float* __restrict__ xd,
       const float* __restrict__ wih,
       const float* __restrict__ whh,
       const float* __restrict__ bias,
       float* __restrict__ out) {
    extern __shared__ uint32_t smem[];
    uint32_t* sW = smem;
    uint32_t* sA = smem + SW_WORDS;
    __half*   sWh = (__half*)sW;

    const int tid  = threadIdx.x;
    const int lane = tid & 31;
    const int warp = tid >> 5;
    const int bt   = blockIdx.x >> 3;
    const int ug   = blockIdx.x & 7;
    const int b0   = bt * 64;
    const int U0   = ug * 32;
    const int mt   = warp & 3;
    const int nh   = warp >> 2;

    // ---- one-time: pack permuted W slice [288 x 96] as f16 B-fragments ----
    // dest: half index = (n*144 + ksp*16 + tig*4 + j)*2 + (kk&1), where
    //   ks = k>>4, ksp = ks>>1, kk = k&15, tig = (kk&7)>>1,
    //   j = (ks&1)*2 + (kk>>3).
    for (int idx = tid; idx < 288 * 96; idx += 256) {
        int k = idx / 96;
        int n = idx - k * 96;              // physical col 0..95
        int nhp = n / 48;
        int nn  = n - nhp * 48;
        int ntp = nn >> 3;
        int c   = nn & 7;
        int j2   = ntp * 2 + (c & 1);
        int gate = j2 % 3;
        int unitw = (c >> 1) * 4 + j2 / 3;
        int gcol = gate * 256 + U0 + nhp * 16 + unitw;
        float v = (k < 256) ? whh[k * 768 + gcol] : wih[(k - 256) * 768 + gcol];
        int ks = k >> 4, kk = k & 15;
        int wordi = n * SWS + (ks >> 1) * 16 + ((kk & 7) >> 1) * 4
                  + (ks & 1) * 2 + (kk >> 3);
        sWh[wordi * 2 + (kk & 1)] = __float2half_rn(v);
    }

    // ---- zero h region of sA (h_0 = 0) ----
    {
        uint4 z = make_uint4(0, 0, 0, 0);
#pragma unroll
        for (int i = 0; i < 8; ++i) {
            int idx = tid + (i << 8);            // 0..2047 uint4
            int m = idx >> 5, q = idx & 31;
            *(uint4*)&sA[m * SAS + q * 4] = z;
        }
    }

    // ---- x staging geometry: row = tid>>2, 8 f16 per thread ----
    const int xrow = tid >> 2;                   // local row 0..63
    const int xco  = (tid & 3) * 8;              // f16 col base 0/8/16/24

    // ---- MMA role & per-thread persistent state ----
    const int gid = lane >> 2;
    const int tig = lane & 3;
    const int row0 = b0 + mt * 16 + gid;          // second row = row0 + 8
    const int ucol = U0 + nh * 16 + tig * 4;      // 4 consecutive units

    float cst[2][4], igr[2][4], bfv[4], bov[4], bgv[4];
    {
        float4 i0 = *(const float4*)&g_igate[row0 * 256 + ucol];
        float4 i1 = *(const float4*)&g_igate[(row0 + 8) * 256 + ucol];
        igr[0][0] = i0.x; igr[0][1] = i0.y; igr[0][2] = i0.z; igr[0][3] = i0.w;
        igr[1][0] = i1.x; igr[1][1] = i1.y; igr[1][2] = i1.z; igr[1][3] = i1.w;
#pragma unroll
        for (int q = 0; q < 4; ++q) {
            cst[0][q] = 0.0f; cst[1][q] = 0.0f;
            bfv[q] = bias[ucol + q];
            bov[q] = bias[256 + ucol + q];
            bgv[q] = bias[512 + ucol + q];
        }
    }

    // ldmatrix source address (per lane): row mt*16 + (lane&15), k-word
    // offset (lane>>4)*4; advance by 8 words per k-step.
    const uint32_t sAsh = (uint32_t)__cvta_generic_to_shared(sA);
    const uint32_t lmat_base =
        sAsh + ((mt * 16 + (lane & 15)) * SAS + (lane >> 4) * 4) * 4;
    const uint32_t* wb0 = sW + (nh * 48 + gid) * SWS + tig * 4;

    int* flag_self = &g_flag[bt * 64 + ug * 8];
    const int* flag_w = &g_flag[bt * 64 + warp * 8];

    // ---- preload x_0 into registers ----
    float4 px0, px1;
    {
        const float* src = &xd[((size_t)(b0 + xrow) * 365 + 0) * 32 + xco];
        px0 = *(const float4*)src;
        px1 = *(const float4*)(src + 4);
    }

    __syncthreads();   // W packed, sA h-region zeroed

    for (int t = 0; t < T_STEPS; ++t) {
        // ---- store x_t from prefetched registers (cvt to f16) ----
        {
            uint4 w;
            w.x = pack_h2(px0.x, px0.y); w.y = pack_h2(px0.z, px0.w);
            w.z = pack_h2(px1.x, px1.y); w.w = pack_h2(px1.z, px1.w);
            *(uint4*)&sA[xrow * SAS + 128 + (xco >> 1)] = w;
        }
        __syncthreads();                                   // s1

        // ---- x-part MMA (ksp 8: k 256..288) while producers finish h_t ----
        float acc[6][4];
#pragma unroll
        for (int nt = 0; nt < 6; ++nt)
#pragma unroll
            for (int q = 0; q < 4; ++q) acc[nt][q] = 0.0f;

        {
            uint32_t aE[4], aO[4];
            asm volatile("ldmatrix.sync.aligned.m8n8.x4.shared.b16 "
                         "{%0,%1,%2,%3}, [%4];"
                         : "=r"(aE[0]), "=r"(aE[1]), "=r"(aE[2]), "=r"(aE[3])
                         : "r"(lmat_base + 16 * 8 * 4));
            asm volatile("ldmatrix.sync.aligned.m8n8.x4.shared.b16 "
                         "{%0,%1,%2,%3}, [%4];"
                         : "=r"(aO[0]), "=r"(aO[1]), "=r"(aO[2]), "=r"(aO[3])
                         : "r"(lmat_base + 17 * 8 * 4));
#pragma unroll
            for (int nt = 0; nt < 6; ++nt) {
                uint4 bq = *(const uint4*)(wb0 + nt * 8 * SWS + 8 * 16);
                mma_f16(acc[nt], aE[0], aE[1], aE[2], aE[3], bq.x, bq.y);
                mma_f16(acc[nt], aO[0], aO[1], aO[2], aO[3], bq.z, bq.w);
            }
        }

        // ---- per-warp: poll producer `warp`, cp.async its h chunk (f16) ----
        if (t > 0) {
            int v;
            do {
                asm volatile("ld.acquire.gpu.global.b32 %0, [%1];"
                             : "=r"(v) : "l"(flag_w) : "memory");
            } while (v < t);
            const __half* hb = g_hbuf[t & 1];
#pragma unroll
            for (int i = 0; i < 8; ++i) {
                int idx = lane + (i << 5);          // 0..255
                int row = idx >> 2;
                int c   = idx & 3;
                const __half* src = &hb[(b0 + row) * 256 + warp * 32 + c * 8];
                uint32_t dst = sAsh + (row * SAS + warp * 16 + c * 4) * 4;
                asm volatile("cp.async.cg.shared.global [%0], [%1], 16;"
                             :: "r"(dst), "l"(src));
            }
            asm volatile("cp.async.commit_group;");
        }

        // ---- prefetch x_{t+1} ----
        if (t + 1 < T_STEPS) {
            const float* src =
                &xd[((size_t)(b0 + xrow) * 365 + (t + 1)) * 32 + xco];
            px0 = *(const float4*)src;
            px1 = *(const float4*)(src + 4);
        }

        if (t > 0) {
            asm volatile("cp.async.wait_group 0;");
            __syncthreads();                               // s3
        }

        // ---- h-part MMA (ksp 0..7: k 0..256) ----
#pragma unroll 4
        for (int ksp = 0; ksp < 8; ++ksp) {
            uint32_t aE[4], aO[4];
            asm volatile("ldmatrix.sync.aligned.m8n8.x4.shared.b16 "
                         "{%0,%1,%2,%3}, [%4];"
                         : "=r"(aE[0]), "=r"(aE[1]), "=r"(aE[2]), "=r"(aE[3])
                         : "r"(lmat_base + (2 * ksp) * 8 * 4));
            asm volatile("ldmatrix.sync.aligned.m8n8.x4.shared.b16 "
                         "{%0,%1,%2,%3}, [%4];"
                         : "=r"(aO[0]), "=r"(aO[1]), "=r"(aO[2]), "=r"(aO[3])
                         : "r"(lmat_base + (2 * ksp + 1) * 8 * 4));
#pragma unroll
            for (int nt = 0; nt < 6; ++nt) {
                uint4 bq = *(const uint4*)(wb0 + nt * 8 * SWS + ksp * 16);
                mma_f16(acc[nt], aE[0], aE[1], aE[2], aE[3], bq.x, bq.y);
                mma_f16(acc[nt], aO[0], aO[1], aO[2], aO[3], bq.z, bq.w);
            }
        }

        // ---- epilogue fully in registers ----
        // per row r (slots sb=2r): unit q gates:
        //  q0: f=acc[0][sb]   o=acc[0][sb+1] g=acc[1][sb]
        //  q1: f=acc[1][sb+1] o=acc[2][sb]   g=acc[2][sb+1]
        //  q2: f=acc[3][sb]   o=acc[3][sb+1] g=acc[4][sb]
        //  q3: f=acc[4][sb+1] o=acc[5][sb]   g=acc[5][sb+1]
        if (t < T_STEPS - 1) {
            __half* hb = g_hbuf[(t + 1) & 1];
#pragma unroll
            for (int r = 0; r < 2; ++r) {
                const int sb = 2 * r;
                float fg[4] = { acc[0][sb],     acc[1][sb + 1],
                                acc[3][sb],     acc[4][sb + 1] };
                float og[4] = { acc[0][sb + 1], acc[2][sb],
                                acc[3][sb + 1], acc[5][sb] };
                float gg[4] = { acc[1][sb],     acc[2][sb + 1],
                                acc[4][sb],     acc[5][sb + 1] };
                float hv[4];
#pragma unroll
                for (int q = 0; q < 4; ++q) {
                    float cn = sig_fast(fg[q] + bfv[q]) * cst[r][q]
                             + igr[r][q] * tanh_fast(gg[q] + bgv[q]);
                    cst[r][q] = cn;
                    hv[q] = sig_fast(og[q] + bov[q]) * tanh_fast(cn);
                }
                uint2 hw;
                hw.x = pack_h2(hv[0], hv[1]);
                hw.y = pack_h2(hv[2], hv[3]);
                *(uint2*)&hb[(row0 + 8 * r) * 256 + ucol] = hw;
            }
            __threadfence();
            __syncthreads();                               // s4
            if (tid == 0)
                asm volatile("st.release.gpu.global.b32 [%0], %1;"
                             :: "l"(flag_self), "r"(t + 1) : "memory");
        } else {
#pragma unroll
            for (int r = 0; r < 2; ++r) {
                const int sb = 2 * r;
                float fg[4] = { acc[0][sb],     acc[1][sb + 1],
                                acc[3][sb],     acc[4][sb + 1] };
                float og[4] = { acc[0][sb + 1], acc[2][sb],
                                acc[3][sb + 1], acc[5][sb] };
                float gg[4] = { acc[1][sb],     acc[2][sb + 1],
                                acc[4][sb],     acc[5][sb + 1] };
                float hv[4];
#pragma unroll
                for (int q = 0; q < 4; ++q) {
                    float cn = sig_fast(fg[q] + bfv[q]) * cst[r][q]
                             + igr[r][q] * tanh_fast(gg[q] + bgv[q]);
                    hv[q] = sig_fast(og[q] + bov[q]) * tanh_fast(cn);
                }
                *(float4*)&out[(row0 + 8 * r) * 256 + ucol] =
                    make_float4(hv[0], hv[1], hv[2], hv[3]);
            }
        }
    }
}

// ---------------------------------------------------------------------------
extern "C" void kernel_launch(void* const* d_in, const int* in_sizes, int n_in,
                              void* d_out, int out_size) {
    const float* xd     = (const float*)d_in[0];   // x_dynamic [1024,365,32]
    const float* xs     = (const float*)d_in[1];   // x_static  [1024,27]
    const float* wih    = (const float*)d_in[2];   // weight_ih [32,768]
    const float* whh    = (const float*)d_in[3];   // weight_hh [256,768]
    const float* wsh    = (const float*)d_in[4];   // weight_sh [27,256]
    const float* bias   = (const float*)d_in[5];   // [768]
    const float* bias_s = (const float*)d_in[6];   // [256]
    float* out = (float*)d_out;                    // [1024,256]

    cudaFuncSetAttribute(lstm_k, cudaFuncAttributeMaxDynamicSharedMemorySize,
                         SMEM_BYTES);

    setup_k<<<1024, 256>>>(xs, wsh, bias_s);
    lstm_k<<<128, 256, SMEM_BYTES>>>(xd, wih, whh, bias, out);
}